// round 2
// baseline (speedup 1.0000x reference)
#include <cuda_runtime.h>

// ---------------------------------------------------------------------------
// Tree-RNN:
//   h = relu(leaf_seqs @ We^T + be)            [8192, 100]
//   13x: h = relu(reshape(h, [n/2,200]) @ W^T + b)
//   out = h_root @ Wp^T + bp                   [1, 2]
//
// Strategy: one generic tiled fp32 GEMM kernel (C = relu(A @ Bt + bias)) with
// packed fma.rn.f32x2 inner loop. Weights are transposed+padded to [K][128]
// once per launch so B loads are coalesced. The pair-concat between levels is
// free: [n,100] row-major reinterpreted as [n/2,200].
// ---------------------------------------------------------------------------

#define THREADS 256
#define BM 64
#define BN 128   // N=100 padded to 128 (padding cols are zero in Bt)
#define BK 8
#define TM 4
#define TN 8

// Scratch (no allocation allowed -> __device__ globals)
__device__ float g_WeT[4096 * 128];   // We [100,4096] -> [4096][128] padded
__device__ float g_WT [200 * 128];    // W  [100,200]  -> [200][128]  padded
__device__ float g_h0 [8192 * 100];
__device__ float g_h1 [4096 * 100];

// dst[k*128 + n] = (n < n_rows) ? src[n*n_cols + k] : 0
__global__ void transpose_pad(const float* __restrict__ src, float* __restrict__ dst,
                              int n_rows, int n_cols) {
    int idx = blockIdx.x * blockDim.x + threadIdx.x;
    if (idx >= n_cols * 128) return;
    int k = idx >> 7;
    int n = idx & 127;
    dst[idx] = (n < n_rows) ? src[n * n_cols + k] : 0.0f;
}

__device__ __forceinline__ unsigned long long splat2(float x) {
    unsigned long long r;
    asm("mov.b64 %0, {%1, %1};" : "=l"(r) : "f"(x));
    return r;
}
__device__ __forceinline__ void fma2(unsigned long long& d,
                                     unsigned long long a, unsigned long long b) {
    asm("fma.rn.f32x2 %0, %1, %2, %0;" : "+l"(d) : "l"(a), "l"(b));
}
__device__ __forceinline__ void unpack2(unsigned long long v, float& lo, float& hi) {
    asm("mov.b64 {%0, %1}, %2;" : "=f"(lo), "=f"(hi) : "l"(v));
}

// C[M,100] = act(A[M,K](lda) @ Bt[K,128] + bias[100]), act = relu if do_relu
__global__ __launch_bounds__(THREADS)
void gemm_bias_relu(const float* __restrict__ A, int lda, int M, int K,
                    const float* __restrict__ Bt,
                    const float* __restrict__ bias,
                    float* __restrict__ C, int do_relu)
{
    __shared__ float As[BM][BK];
    __shared__ float Bs[BK][BN];

    const int tid  = threadIdx.x;
    const int tx   = tid & 15;    // 16 col-groups of TN=8
    const int ty   = tid >> 4;    // 16 row-groups of TM=4
    const int row0 = blockIdx.x * BM;

    unsigned long long acc[TM][TN / 2];
#pragma unroll
    for (int i = 0; i < TM; i++)
#pragma unroll
        for (int j = 0; j < TN / 2; j++) acc[i][j] = 0ull;

    // A tile load coords: 512 floats = 256 float2; am = row in tile, ak = k pair
    const int am = tid >> 2;
    const int ak = (tid & 3) * 2;
    // B tile load coords: 1024 floats = 256 float4
    const int bk = tid >> 5;
    const int bn = (tid & 31) * 4;

    for (int k0 = 0; k0 < K; k0 += BK) {
        float2 av = make_float2(0.0f, 0.0f);
        if (row0 + am < M)
            av = *reinterpret_cast<const float2*>(
                &A[(size_t)(row0 + am) * lda + k0 + ak]);
        As[am][ak]     = av.x;
        As[am][ak + 1] = av.y;

        float4 bv = *reinterpret_cast<const float4*>(&Bt[(size_t)(k0 + bk) * BN + bn]);
        *reinterpret_cast<float4*>(&Bs[bk][bn]) = bv;
        __syncthreads();

#pragma unroll
        for (int k = 0; k < BK; k++) {
            unsigned long long a2[TM];
#pragma unroll
            for (int i = 0; i < TM; i++) a2[i] = splat2(As[ty * TM + i][k]);

            const unsigned long long* bp =
                reinterpret_cast<const unsigned long long*>(&Bs[k][tx * TN]);
            unsigned long long b2[TN / 2];
#pragma unroll
            for (int j = 0; j < TN / 2; j++) b2[j] = bp[j];

#pragma unroll
            for (int i = 0; i < TM; i++)
#pragma unroll
                for (int j = 0; j < TN / 2; j++) fma2(acc[i][j], a2[i], b2[j]);
        }
        __syncthreads();
    }

#pragma unroll
    for (int i = 0; i < TM; i++) {
        int row = row0 + ty * TM + i;
        if (row >= M) continue;
#pragma unroll
        for (int j = 0; j < TN / 2; j++) {
            float lo, hi;
            unpack2(acc[i][j], lo, hi);
            int n = tx * TN + 2 * j;
            if (n < 100) {
                float v = lo + bias[n];
                if (do_relu) v = fmaxf(v, 0.0f);
                C[(size_t)row * 100 + n] = v;
            }
            if (n + 1 < 100) {
                float v = hi + bias[n + 1];
                if (do_relu) v = fmaxf(v, 0.0f);
                C[(size_t)row * 100 + n + 1] = v;
            }
        }
    }
}

// out[c] = h[0:100] . Wp[c,:] + bp[c], c = 0,1
__global__ void root_proj(const float* __restrict__ h, const float* __restrict__ Wp,
                          const float* __restrict__ bp, float* __restrict__ out) {
    int c    = threadIdx.y;  // 2
    int lane = threadIdx.x;  // 32
    float s = 0.0f;
    for (int k = lane; k < 100; k += 32) s += Wp[c * 100 + k] * h[k];
#pragma unroll
    for (int o = 16; o > 0; o >>= 1) s += __shfl_down_sync(0xffffffffu, s, o);
    if (lane == 0) out[c] = s + bp[c];
}

extern "C" void kernel_launch(void* const* d_in, const int* in_sizes, int n_in,
                              void* d_out, int out_size) {
    const float* leaf = (const float*)d_in[0];  // [8192, 4096]
    const float* We   = (const float*)d_in[1];  // [100, 4096]
    const float* be   = (const float*)d_in[2];  // [100]
    const float* W    = (const float*)d_in[3];  // [100, 200]
    const float* b    = (const float*)d_in[4];  // [100]
    const float* Wp   = (const float*)d_in[5];  // [2, 100]
    const float* bp   = (const float*)d_in[6];  // [2]
    float* out = (float*)d_out;                 // [2]

    float *WeT, *WT, *h0, *h1;
    cudaGetSymbolAddress((void**)&WeT, g_WeT);
    cudaGetSymbolAddress((void**)&WT,  g_WT);
    cudaGetSymbolAddress((void**)&h0,  g_h0);
    cudaGetSymbolAddress((void**)&h1,  g_h1);

    transpose_pad<<<(4096 * 128 + 255) / 256, 256>>>(We, WeT, 100, 4096);
    transpose_pad<<<(200 * 128 + 255) / 256, 256>>>(W, WT, 100, 200);

    // Leaf embedding: [8192,4096] @ [4096,100] -> h0
    gemm_bias_relu<<<8192 / BM, THREADS>>>(leaf, 4096, 8192, 4096, WeT, be, h0, 1);

    // 13 tree levels: [n/2,200] @ [200,100]
    float* cur = h0;
    float* nxt = h1;
    int n = 8192;
    for (int lvl = 0; lvl < 13; lvl++) {
        int m = n / 2;
        gemm_bias_relu<<<(m + BM - 1) / BM, THREADS>>>(cur, 200, m, 200, WT, b, nxt, 1);
        float* t = cur; cur = nxt; nxt = t;
        n = m;
    }

    root_proj<<<1, dim3(32, 2)>>>(cur, Wp, bp, out);
}

// round 3
// speedup vs baseline: 2.0243x; 2.0243x over previous
#include <cuda_runtime.h>

// ---------------------------------------------------------------------------
// Tree-RNN, round 2:
//   1) leaf GEMM [8192,4096]x[4096,100]: specialized tiled fp32 kernel with
//      cp.async double buffering + packed fma.rn.f32x2  (compute-bound target)
//   2) all 13 tree levels + root projection fused in ONE persistent kernel
//      with an all-resident grid barrier (weights live in shared memory)
// ---------------------------------------------------------------------------

#define LBM 64
#define LBN 128
#define LBK 16
#define LTHREADS 256
#define TG 128            // tree kernel grid (all resident on 148 SMs)

// scratch (allocation forbidden -> device globals)
__device__ float g_WeT[4096 * 128];   // We [100,4096] -> [4096][128] padded, k-major
__device__ float g_WTt[200 * 100];    // W  [100,200]  -> [200][100] k-major
__device__ float g_h0 [8192 * 100];
__device__ float g_h1 [4096 * 100];

// barrier state (monotonic epoch survives graph replays safely)
__device__ unsigned g_cnt = 0;
__device__ volatile unsigned g_epoch = 0;

// ------------------------------ helpers -----------------------------------
__device__ __forceinline__ unsigned long long splat2(float x) {
    unsigned long long r;
    asm("mov.b64 %0, {%1, %1};" : "=l"(r) : "f"(x));
    return r;
}
__device__ __forceinline__ void fma2(unsigned long long& d,
                                     unsigned long long a, unsigned long long b) {
    asm("fma.rn.f32x2 %0, %1, %2, %0;" : "+l"(d) : "l"(a), "l"(b));
}
__device__ __forceinline__ void unpack2(unsigned long long v, float& lo, float& hi) {
    asm("mov.b64 {%0, %1}, %2;" : "=f"(lo), "=f"(hi) : "l"(v));
}
__device__ __forceinline__ void cp16(float* s, const float* g) {
    unsigned sa = (unsigned)__cvta_generic_to_shared(s);
    asm volatile("cp.async.ca.shared.global [%0], [%1], 16;" :: "r"(sa), "l"(g));
}
__device__ __forceinline__ void cp_commit() {
    asm volatile("cp.async.commit_group;");
}
template <int N>
__device__ __forceinline__ void cp_wait() {
    asm volatile("cp.async.wait_group %0;" :: "n"(N));
}

// ------------------------- weight preprocessing ----------------------------
// g_WeT[k*128 + n] = (n<100) ? We[n*4096 + k] : 0
__global__ void prep_WeT(const float* __restrict__ We, float* __restrict__ dst) {
    int idx = blockIdx.x * blockDim.x + threadIdx.x;
    if (idx >= 4096 * 128) return;
    int k = idx >> 7, n = idx & 127;
    dst[idx] = (n < 100) ? We[n * 4096 + k] : 0.0f;
}
// g_WTt[k*100 + n] = W[n*200 + k]
__global__ void prep_WTt(const float* __restrict__ W, float* __restrict__ dst) {
    int idx = blockIdx.x * blockDim.x + threadIdx.x;
    if (idx >= 200 * 100) return;
    int k = idx / 100, n = idx % 100;
    dst[idx] = W[n * 200 + k];
}

// --------------------------- leaf GEMM -------------------------------------
// C[8192,100] = relu(A[8192,4096] @ Bt[4096,128][:, :100] + bias)
__global__ __launch_bounds__(LTHREADS)
void leaf_gemm(const float* __restrict__ A, const float* __restrict__ Bt,
               const float* __restrict__ bias, float* __restrict__ C)
{
    __shared__ float As[2][LBM][LBK];   // row-major A tile
    __shared__ float Bs[2][LBK][LBN];

    const int tid  = threadIdx.x;
    const int tx   = tid & 15;          // 16 col groups of TN=8
    const int ty   = tid >> 4;          // 16 row groups of TM=4
    const int row0 = blockIdx.x * LBM;

    // A tile: 64x16 floats = 256 float4; one per thread
    const int am  = tid >> 2;
    const int akq = (tid & 3) * 4;
    // B tile: 16x128 floats = 512 float4; two per thread
    const int bk0 = tid >> 5;
    const int bn0 = (tid & 31) * 4;
    const int bk1 = bk0 + 8;

    unsigned long long acc[4][4];
#pragma unroll
    for (int i = 0; i < 4; i++)
#pragma unroll
        for (int j = 0; j < 4; j++) acc[i][j] = 0ull;

    // prologue: stage 0
    {
        const int k0 = 0;
        cp16(&As[0][am][akq], &A[(size_t)(row0 + am) * 4096 + k0 + akq]);
        cp16(&Bs[0][bk0][bn0], &Bt[(size_t)(k0 + bk0) * LBN + bn0]);
        cp16(&Bs[0][bk1][bn0], &Bt[(size_t)(k0 + bk1) * LBN + bn0]);
        cp_commit();
    }

    const int ITERS = 4096 / LBK;  // 256
    for (int i = 0; i < ITERS; i++) {
        if (i + 1 < ITERS) {
            const int k0 = (i + 1) * LBK;
            const int st = (i + 1) & 1;
            cp16(&As[st][am][akq], &A[(size_t)(row0 + am) * 4096 + k0 + akq]);
            cp16(&Bs[st][bk0][bn0], &Bt[(size_t)(k0 + bk0) * LBN + bn0]);
            cp16(&Bs[st][bk1][bn0], &Bt[(size_t)(k0 + bk1) * LBN + bn0]);
            cp_commit();
            cp_wait<1>();     // tile i ready, tile i+1 in flight
        } else {
            cp_wait<0>();
        }
        __syncthreads();

        const int st = i & 1;
#pragma unroll
        for (int k = 0; k < LBK; k++) {
            unsigned long long a2[4];
#pragma unroll
            for (int m = 0; m < 4; m++) a2[m] = splat2(As[st][ty * 4 + m][k]);

            const unsigned long long* bp =
                reinterpret_cast<const unsigned long long*>(&Bs[st][k][tx * 8]);
            unsigned long long b2[4];
#pragma unroll
            for (int j = 0; j < 4; j++) b2[j] = bp[j];

#pragma unroll
            for (int m = 0; m < 4; m++)
#pragma unroll
                for (int j = 0; j < 4; j++) fma2(acc[m][j], a2[m], b2[j]);
        }
        __syncthreads();
    }

#pragma unroll
    for (int m = 0; m < 4; m++) {
        const int row = row0 + ty * 4 + m;
#pragma unroll
        for (int j = 0; j < 4; j++) {
            float lo, hi;
            unpack2(acc[m][j], lo, hi);
            int n = tx * 8 + 2 * j;
            if (n < 100)
                C[(size_t)row * 100 + n] = fmaxf(lo + bias[n], 0.0f);
            if (n + 1 < 100)
                C[(size_t)row * 100 + n + 1] = fmaxf(hi + bias[n + 1], 0.0f);
        }
    }
}

// ----------------------- persistent tree kernel ----------------------------
__device__ __forceinline__ void grid_barrier() {
    __syncthreads();
    if (threadIdx.x == 0) {
        unsigned e = g_epoch;
        __threadfence();
        if (atomicAdd(&g_cnt, 1u) == TG - 1) {
            g_cnt = 0;
            __threadfence();
            g_epoch = e + 1;
        } else {
            while (g_epoch == e) { __nanosleep(32); }
        }
        __threadfence();
    }
    __syncthreads();
}

// smem: Ws[200*100] | xs[16][200] | sb[100]
__global__ __launch_bounds__(256)
void tree_kernel(const float* __restrict__ Wt, const float* __restrict__ b,
                 const float* __restrict__ Wp, const float* __restrict__ bp,
                 float* __restrict__ h0, float* __restrict__ h1,
                 float* __restrict__ out)
{
    extern __shared__ float sm[];
    float* Ws = sm;                                  // 20000
    float (*xs)[200] = (float(*)[200])(sm + 20000);  // 16*200 = 3200
    float* sb = sm + 20000 + 3200;                   // 100

    for (int i = threadIdx.x; i < 20000; i += 256) Ws[i] = Wt[i];
    if (threadIdx.x < 100) sb[threadIdx.x] = b[threadIdx.x];
    __syncthreads();

    const int n  = threadIdx.x & 127;
    const int rg = threadIdx.x >> 7;   // 0/1: which 8-row group

    float* cur = h0;
    float* nxt = h1;
    int m = 8192;

    for (int lvl = 0; lvl < 13; lvl++) {
        const int mo = m >> 1;
        const int ntiles = (mo + 15) >> 4;

        for (int t = blockIdx.x; t < ntiles; t += TG) {
            const int r0   = t * 16;
            const int rows = min(16, mo - r0);

            // stage input pairs: contiguous [rows,200] from cur (L2 via .cg)
            {
                const float4* src = reinterpret_cast<const float4*>(cur + (size_t)r0 * 200);
                float4* dst = reinterpret_cast<float4*>(&xs[0][0]);
                const int tot = rows * 50;
                for (int i = threadIdx.x; i < tot; i += 256) dst[i] = __ldcg(src + i);
            }
            __syncthreads();

            float acc[8];
#pragma unroll
            for (int r = 0; r < 8; r++) acc[r] = 0.0f;

            if (n < 100) {
#pragma unroll 5
                for (int k0 = 0; k0 < 200; k0 += 8) {
                    float w[8];
#pragma unroll
                    for (int j = 0; j < 8; j++) w[j] = Ws[(k0 + j) * 100 + n];
#pragma unroll
                    for (int r = 0; r < 8; r++) {
                        const int rr = rg * 8 + r;
                        float4 x0 = *reinterpret_cast<const float4*>(&xs[rr][k0]);
                        float4 x1 = *reinterpret_cast<const float4*>(&xs[rr][k0 + 4]);
                        acc[r] = fmaf(x0.x, w[0], acc[r]);
                        acc[r] = fmaf(x0.y, w[1], acc[r]);
                        acc[r] = fmaf(x0.z, w[2], acc[r]);
                        acc[r] = fmaf(x0.w, w[3], acc[r]);
                        acc[r] = fmaf(x1.x, w[4], acc[r]);
                        acc[r] = fmaf(x1.y, w[5], acc[r]);
                        acc[r] = fmaf(x1.z, w[6], acc[r]);
                        acc[r] = fmaf(x1.w, w[7], acc[r]);
                    }
                }
#pragma unroll
                for (int r = 0; r < 8; r++) {
                    const int rr = rg * 8 + r;
                    if (rr < rows)
                        nxt[(size_t)(r0 + rr) * 100 + n] = fmaxf(acc[r] + sb[n], 0.0f);
                }
            }
            __syncthreads();
        }

        grid_barrier();
        float* tmp = cur; cur = nxt; nxt = tmp;
        m = mo;
    }

    // root projection: cur holds 1 row of 100
    if (blockIdx.x == 0 && threadIdx.x < 64) {
        const int c    = threadIdx.x >> 5;
        const int lane = threadIdx.x & 31;
        float s = 0.0f;
        for (int k = lane; k < 100; k += 32) s += Wp[c * 100 + k] * __ldcg(&cur[k]);
#pragma unroll
        for (int o = 16; o > 0; o >>= 1) s += __shfl_down_sync(0xffffffffu, s, o);
        if (lane == 0) out[c] = s + bp[c];
    }
}

// ------------------------------ launch -------------------------------------
extern "C" void kernel_launch(void* const* d_in, const int* in_sizes, int n_in,
                              void* d_out, int out_size) {
    const float* leaf = (const float*)d_in[0];  // [8192, 4096]
    const float* We   = (const float*)d_in[1];  // [100, 4096]
    const float* be   = (const float*)d_in[2];  // [100]
    const float* W    = (const float*)d_in[3];  // [100, 200]
    const float* b    = (const float*)d_in[4];  // [100]
    const float* Wp   = (const float*)d_in[5];  // [2, 100]
    const float* bp   = (const float*)d_in[6];  // [2]
    float* out = (float*)d_out;                 // [2]

    float *WeT, *WTt, *h0, *h1;
    cudaGetSymbolAddress((void**)&WeT, g_WeT);
    cudaGetSymbolAddress((void**)&WTt, g_WTt);
    cudaGetSymbolAddress((void**)&h0,  g_h0);
    cudaGetSymbolAddress((void**)&h1,  g_h1);

    static int smem_set = 0;
    const int TREE_SMEM = (20000 + 3200 + 100) * 4;  // 93200 B
    if (!smem_set) {
        cudaFuncSetAttribute(tree_kernel,
                             cudaFuncAttributeMaxDynamicSharedMemorySize, TREE_SMEM);
        smem_set = 1;
    }

    prep_WeT<<<(4096 * 128 + 255) / 256, 256>>>(We, WeT);
    prep_WTt<<<(200 * 100 + 255) / 256, 256>>>(W, WTt);

    leaf_gemm<<<8192 / LBM, LTHREADS>>>(leaf, WeT, be, h0);

    tree_kernel<<<TG, 256, TREE_SMEM>>>(WTt, b, Wp, bp, h0, h1, out);
}

// round 7
// speedup vs baseline: 4.7808x; 2.3616x over previous
#include <cuda_runtime.h>
#include <cuda_bf16.h>
#include <cstdint>

// ===========================================================================
// Tree-RNN round 5: R4 with the B-operand ldmatrix fixed (non-trans — B is
// stored [N][K] k-contiguous = col-major KxN, which is what mma .col wants).
// Leaf GEMM: mma.sync.m16n8k16 bf16, 3-term bf16 split for fp32 accuracy.
// Tree levels: 3-kernel cascade, weights in smem.
// ===========================================================================

// ----------------------------- scratch ------------------------------------
__device__ __nv_bfloat16 g_Bhi[128 * 4096];  // We padded to 128 rows, bf16 hi
__device__ __nv_bfloat16 g_Blo[128 * 4096];  // residual lo
__device__ float g_WTt[200 * 100];           // W k-major
__device__ float g_h0[8192 * 100];
__device__ float g_t1[256 * 100];
__device__ float g_t2[16 * 100];

// ----------------------------- helpers ------------------------------------
__device__ __forceinline__ void cp16(uint32_t saddr, const void* g) {
    asm volatile("cp.async.cg.shared.global [%0], [%1], 16;" :: "r"(saddr), "l"(g));
}
__device__ __forceinline__ void cp_commit() { asm volatile("cp.async.commit_group;"); }
__device__ __forceinline__ void cp_wait0()  { asm volatile("cp.async.wait_group 0;"); }

__device__ __forceinline__ void ldsm_x4(uint32_t& r0, uint32_t& r1, uint32_t& r2,
                                        uint32_t& r3, uint32_t addr) {
    asm volatile("ldmatrix.sync.aligned.m8n8.x4.shared.b16 {%0,%1,%2,%3}, [%4];"
                 : "=r"(r0), "=r"(r1), "=r"(r2), "=r"(r3) : "r"(addr));
}
__device__ __forceinline__ void mma16816(float* c, const uint32_t* a, const uint32_t* b) {
    asm volatile(
        "mma.sync.aligned.m16n8k16.row.col.f32.bf16.bf16.f32 "
        "{%0,%1,%2,%3}, {%4,%5,%6,%7}, {%8,%9}, {%0,%1,%2,%3};"
        : "+f"(c[0]), "+f"(c[1]), "+f"(c[2]), "+f"(c[3])
        : "r"(a[0]), "r"(a[1]), "r"(a[2]), "r"(a[3]), "r"(b[0]), "r"(b[1]));
}

// ----------------------------- prep kernels --------------------------------
// We is [100,4096] row-major = k-major per output row already. Pad to 128 rows.
__global__ void prep_B(const float* __restrict__ We,
                       __nv_bfloat16* __restrict__ bhi, __nv_bfloat16* __restrict__ blo) {
    int idx = blockIdx.x * blockDim.x + threadIdx.x;
    if (idx >= 128 * 4096) return;
    int n = idx >> 12;
    float v = (n < 100) ? We[idx] : 0.0f;
    __nv_bfloat16 h = __float2bfloat16(v);
    bhi[idx] = h;
    blo[idx] = __float2bfloat16(v - __bfloat162float(h));
}
__global__ void prep_WTt(const float* __restrict__ W, float* __restrict__ dst) {
    int idx = blockIdx.x * blockDim.x + threadIdx.x;
    if (idx >= 200 * 100) return;
    int k = idx / 100, n = idx % 100;
    dst[idx] = W[n * 200 + k];
}

// ----------------------------- leaf GEMM -----------------------------------
// C[8192,100] = relu(A[8192,4096] @ WeT + bias)
// BM=64, BN=128, BK=32; 8 warps as 2(M) x 4(N), warp tile 32x32.
// smem rows padded: 40 bf16 = 80 B per row (16B aligned).
#define ROWB      80
#define LSM_AHI   0
#define LSM_ALO   (64 * ROWB)            // 5120
#define LSM_BHI   (2 * 64 * ROWB)        // 10240
#define LSM_BLO   (LSM_BHI + 128 * ROWB) // 20480
#define LSM_STAGE (LSM_BLO + 128 * ROWB) // 30720
#define LEAF_SMEM (2 * LSM_STAGE)        // 61440

__global__ __launch_bounds__(256)
void leaf_gemm_mma(const float* __restrict__ A,
                   const __nv_bfloat16* __restrict__ Bhi,
                   const __nv_bfloat16* __restrict__ Blo,
                   const float* __restrict__ bias,
                   float* __restrict__ C) {
    extern __shared__ char smem[];
    const uint32_t sbase = (uint32_t)__cvta_generic_to_shared(smem);

    const int tid  = threadIdx.x;
    const int lane = tid & 31;
    const int wid  = tid >> 5;
    const int wm   = wid >> 2;       // 0..1
    const int wn   = wid & 3;        // 0..3
    const int row0 = blockIdx.x * 64;

    // ldmatrix per-lane offsets
    const int mat = lane >> 3, r8 = lane & 7;
    // A (non-trans): mat0=(m0-7,k0-7) mat1=(m8-15,k0-7) mat2=(m0-7,k8-15) mat3=(m8-15,k8-15)
    uint32_t aoff[2];
#pragma unroll
    for (int mt = 0; mt < 2; mt++) {
        int arow = wm * 32 + mt * 16 + (mat & 1) * 8 + r8;
        aoff[mt] = (uint32_t)(arow * ROWB + (mat >> 1) * 16);
    }
    // B (non-trans, [N][K] k-contiguous): mat0=n0-7@k0, mat1=n0-7@k8,
    // mat2=n8-15@k0, mat3=n8-15@k8  -> regs {b0(k0),b1(k8)} per n-octet.
    uint32_t boff[2];
#pragma unroll
    for (int nt = 0; nt < 2; nt++) {
        int brow = wn * 32 + nt * 16 + (mat >> 1) * 8 + r8;
        boff[nt] = (uint32_t)(brow * ROWB + (mat & 1) * 16);
    }

    // A global load mapping: 64 rows x 32 k fp32, 8 floats/thread
    const int  ar  = tid >> 2;            // 0..63
    const int  aks = tid & 3;             // 0..3 (8 floats each)
    const float* agp = A + (size_t)(row0 + ar) * 4096 + aks * 8;

    float acc[2][4][4];
#pragma unroll
    for (int mt = 0; mt < 2; mt++)
#pragma unroll
        for (int j = 0; j < 4; j++)
#pragma unroll
            for (int c = 0; c < 4; c++) acc[mt][j][c] = 0.0f;

    float4 av0, av1;

    // ---- prologue: chunk 0 ----
    {
        const uint32_t st = sbase;
#pragma unroll
        for (int q = 0; q < 2; q++) {
            int idx = tid + q * 256;
            int brow = idx >> 2, seg = idx & 3;
            uint32_t dof = (uint32_t)(brow * ROWB + seg * 16);
            size_t gof = (size_t)brow * 4096 + seg * 8;
            cp16(st + LSM_BHI + dof, Bhi + gof);
            cp16(st + LSM_BLO + dof, Blo + gof);
        }
        cp_commit();
        av0 = *(const float4*)(agp);
        av1 = *(const float4*)(agp + 4);
        __nv_bfloat162 h0 = __float22bfloat162_rn(make_float2(av0.x, av0.y));
        __nv_bfloat162 h1 = __float22bfloat162_rn(make_float2(av0.z, av0.w));
        __nv_bfloat162 h2 = __float22bfloat162_rn(make_float2(av1.x, av1.y));
        __nv_bfloat162 h3 = __float22bfloat162_rn(make_float2(av1.z, av1.w));
        float2 f0 = __bfloat1622float2(h0), f1 = __bfloat1622float2(h1);
        float2 f2 = __bfloat1622float2(h2), f3 = __bfloat1622float2(h3);
        __nv_bfloat162 l0 = __float22bfloat162_rn(make_float2(av0.x - f0.x, av0.y - f0.y));
        __nv_bfloat162 l1 = __float22bfloat162_rn(make_float2(av0.z - f1.x, av0.w - f1.y));
        __nv_bfloat162 l2 = __float22bfloat162_rn(make_float2(av1.x - f2.x, av1.y - f2.y));
        __nv_bfloat162 l3 = __float22bfloat162_rn(make_float2(av1.z - f3.x, av1.w - f3.y));
        uint4 hv = make_uint4(*(uint32_t*)&h0, *(uint32_t*)&h1, *(uint32_t*)&h2, *(uint32_t*)&h3);
        uint4 lv = make_uint4(*(uint32_t*)&l0, *(uint32_t*)&l1, *(uint32_t*)&l2, *(uint32_t*)&l3);
        uint32_t dof = (uint32_t)(ar * ROWB + aks * 16);
        *(uint4*)(smem + LSM_AHI + dof) = hv;
        *(uint4*)(smem + LSM_ALO + dof) = lv;
    }

    for (int i = 0; i < 128; i++) {
        const int s = i & 1;
        const uint32_t st = sbase + s * LSM_STAGE;
        const uint32_t nst = sbase + (s ^ 1) * LSM_STAGE;
        char* nst_gen = smem + (s ^ 1) * LSM_STAGE;

        cp_wait0();          // B chunk i resident
        __syncthreads();     // A chunk i STS visible; stage s^1 free

        if (i < 127) {
            const size_t kof = (size_t)(i + 1) * 32;
#pragma unroll
            for (int q = 0; q < 2; q++) {
                int idx = tid + q * 256;
                int brow = idx >> 2, seg = idx & 3;
                uint32_t dof = (uint32_t)(brow * ROWB + seg * 16);
                size_t gof = (size_t)brow * 4096 + kof + seg * 8;
                cp16(nst + LSM_BHI + dof, Bhi + gof);
                cp16(nst + LSM_BLO + dof, Blo + gof);
            }
            cp_commit();
            av0 = *(const float4*)(agp + kof);
            av1 = *(const float4*)(agp + kof + 4);
        }

        // ---- compute chunk i (2 x k16 steps) ----
#pragma unroll
        for (int kk = 0; kk < 2; kk++) {
            const uint32_t kb = (uint32_t)(kk * 32);
            uint32_t ah[2][4], al[2][4], bh[2][4], bl[2][4];
#pragma unroll
            for (int mt = 0; mt < 2; mt++) {
                ldsm_x4(ah[mt][0], ah[mt][1], ah[mt][2], ah[mt][3],
                        st + LSM_AHI + aoff[mt] + kb);
                ldsm_x4(al[mt][0], al[mt][1], al[mt][2], al[mt][3],
                        st + LSM_ALO + aoff[mt] + kb);
            }
#pragma unroll
            for (int nt = 0; nt < 2; nt++) {
                ldsm_x4(bh[nt][0], bh[nt][1], bh[nt][2], bh[nt][3],
                        st + LSM_BHI + boff[nt] + kb);
                ldsm_x4(bl[nt][0], bl[nt][1], bl[nt][2], bl[nt][3],
                        st + LSM_BLO + boff[nt] + kb);
            }
#pragma unroll
            for (int mt = 0; mt < 2; mt++)
#pragma unroll
                for (int j = 0; j < 4; j++) {
                    const int x4 = j >> 1, p = (j & 1) * 2;
                    uint32_t bhr[2] = {bh[x4][p], bh[x4][p + 1]};
                    uint32_t blr[2] = {bl[x4][p], bl[x4][p + 1]};
                    mma16816(acc[mt][j], ah[mt], bhr);   // hi*hi
                    mma16816(acc[mt][j], ah[mt], blr);   // hi*lo
                    mma16816(acc[mt][j], al[mt], bhr);   // lo*hi
                }
        }

        // ---- convert + STS A chunk i+1 into stage s^1 ----
        if (i < 127) {
            __nv_bfloat162 h0 = __float22bfloat162_rn(make_float2(av0.x, av0.y));
            __nv_bfloat162 h1 = __float22bfloat162_rn(make_float2(av0.z, av0.w));
            __nv_bfloat162 h2 = __float22bfloat162_rn(make_float2(av1.x, av1.y));
            __nv_bfloat162 h3 = __float22bfloat162_rn(make_float2(av1.z, av1.w));
            float2 f0 = __bfloat1622float2(h0), f1 = __bfloat1622float2(h1);
            float2 f2 = __bfloat1622float2(h2), f3 = __bfloat1622float2(h3);
            __nv_bfloat162 l0 = __float22bfloat162_rn(make_float2(av0.x - f0.x, av0.y - f0.y));
            __nv_bfloat162 l1 = __float22bfloat162_rn(make_float2(av0.z - f1.x, av0.w - f1.y));
            __nv_bfloat162 l2 = __float22bfloat162_rn(make_float2(av1.x - f2.x, av1.y - f2.y));
            __nv_bfloat162 l3 = __float22bfloat162_rn(make_float2(av1.z - f3.x, av1.w - f3.y));
            uint4 hv = make_uint4(*(uint32_t*)&h0, *(uint32_t*)&h1, *(uint32_t*)&h2, *(uint32_t*)&h3);
            uint4 lv = make_uint4(*(uint32_t*)&l0, *(uint32_t*)&l1, *(uint32_t*)&l2, *(uint32_t*)&l3);
            uint32_t dof = (uint32_t)(ar * ROWB + aks * 16);
            *(uint4*)(nst_gen + LSM_AHI + dof) = hv;
            *(uint4*)(nst_gen + LSM_ALO + dof) = lv;
        }
    }

    // ---- epilogue: bias + relu, write C [*,100] ----
#pragma unroll
    for (int mt = 0; mt < 2; mt++) {
        const int row = row0 + wm * 32 + mt * 16 + (lane >> 2);
#pragma unroll
        for (int j = 0; j < 4; j++) {
            const int col = wn * 32 + j * 8 + (lane & 3) * 2;
#pragma unroll
            for (int c = 0; c < 4; c++) {
                const int rr = row + (c >> 1) * 8;
                const int cc = col + (c & 1);
                if (cc < 100)
                    C[(size_t)rr * 100 + cc] =
                        fmaxf(acc[mt][j][c] + __ldg(bias + cc), 0.0f);
            }
        }
    }
}

// ----------------------------- tree cascade --------------------------------
#define TREE_SMEM ((20000 + 100 + 3200 + 1600) * 4)

__device__ __forceinline__ void run_level(const float* __restrict__ Ws,
                                          const float* __restrict__ sb,
                                          const float* __restrict__ xin,
                                          float* __restrict__ xout, int m_out) {
    const int n = threadIdx.x & 127;
    const int half = threadIdx.x >> 7;
    if (n < 100) {
        float acc[8];
#pragma unroll
        for (int c = 0; c < 8; c++) acc[c] = 0.0f;
        for (int k0 = 0; k0 < 200; k0 += 8) {
            float w[8];
#pragma unroll
            for (int j = 0; j < 8; j++) w[j] = Ws[(k0 + j) * 100 + n];
#pragma unroll
            for (int c = 0; c < 8; c++) {
                int nd = half + 2 * c;
                if (nd < m_out) {
                    float4 x0 = *(const float4*)(xin + nd * 200 + k0);
                    float4 x1 = *(const float4*)(xin + nd * 200 + k0 + 4);
                    acc[c] = fmaf(x0.x, w[0], acc[c]);
                    acc[c] = fmaf(x0.y, w[1], acc[c]);
                    acc[c] = fmaf(x0.z, w[2], acc[c]);
                    acc[c] = fmaf(x0.w, w[3], acc[c]);
                    acc[c] = fmaf(x1.x, w[4], acc[c]);
                    acc[c] = fmaf(x1.y, w[5], acc[c]);
                    acc[c] = fmaf(x1.z, w[6], acc[c]);
                    acc[c] = fmaf(x1.w, w[7], acc[c]);
                }
            }
        }
#pragma unroll
        for (int c = 0; c < 8; c++) {
            int nd = half + 2 * c;
            if (nd < m_out) xout[nd * 100 + n] = fmaxf(acc[c] + sb[n], 0.0f);
        }
    }
    __syncthreads();
}

template <int ROWS_IN, int NLEV>
__device__ __forceinline__ const float* tree_body(const float* __restrict__ in_rows,
                                                  const float* __restrict__ Wt,
                                                  const float* __restrict__ b,
                                                  float* sm) {
    float* Ws   = sm;
    float* sb   = sm + 20000;
    float* bufA = sm + 20100;
    float* bufB = sm + 23300;

    for (int i = threadIdx.x; i < 20000; i += 256) Ws[i] = Wt[i];
    if (threadIdx.x < 100) sb[threadIdx.x] = b[threadIdx.x];
    for (int i = threadIdx.x; i < ROWS_IN * 100; i += 256) bufA[i] = in_rows[i];
    __syncthreads();

    const float* cur = bufA;
    float* nxt = bufB;
    int m = ROWS_IN;
#pragma unroll
    for (int l = 0; l < NLEV; l++) {
        run_level(Ws, sb, cur, nxt, m >> 1);
        const float* t = cur; cur = nxt; nxt = (float*)t;
        m >>= 1;
    }
    return cur;
}

__global__ __launch_bounds__(256)
void tree_stage1(const float* __restrict__ in, float* __restrict__ out,
                 const float* __restrict__ Wt, const float* __restrict__ b) {
    extern __shared__ float sm[];
    const float* res = tree_body<32, 5>(in + (size_t)blockIdx.x * 3200, Wt, b, sm);
    if (threadIdx.x < 100) out[blockIdx.x * 100 + threadIdx.x] = res[threadIdx.x];
}
__global__ __launch_bounds__(256)
void tree_stage2(const float* __restrict__ in, float* __restrict__ out,
                 const float* __restrict__ Wt, const float* __restrict__ b) {
    extern __shared__ float sm[];
    const float* res = tree_body<16, 4>(in + (size_t)blockIdx.x * 1600, Wt, b, sm);
    if (threadIdx.x < 100) out[blockIdx.x * 100 + threadIdx.x] = res[threadIdx.x];
}
__global__ __launch_bounds__(256)
void tree_stage3(const float* __restrict__ in, float* __restrict__ out,
                 const float* __restrict__ Wt, const float* __restrict__ b,
                 const float* __restrict__ Wp, const float* __restrict__ bp) {
    extern __shared__ float sm[];
    const float* res = tree_body<16, 4>(in, Wt, b, sm);
    if (threadIdx.x < 64) {
        const int c = threadIdx.x >> 5;
        const int lane = threadIdx.x & 31;
        float s = 0.0f;
        for (int k = lane; k < 100; k += 32) s += Wp[c * 100 + k] * res[k];
#pragma unroll
        for (int o = 16; o > 0; o >>= 1) s += __shfl_down_sync(0xffffffffu, s, o);
        if (lane == 0) out[c] = s + bp[c];
    }
}

// ------------------------------ launch -------------------------------------
extern "C" void kernel_launch(void* const* d_in, const int* in_sizes, int n_in,
                              void* d_out, int out_size) {
    const float* leaf = (const float*)d_in[0];  // [8192, 4096]
    const float* We   = (const float*)d_in[1];  // [100, 4096]
    const float* be   = (const float*)d_in[2];  // [100]
    const float* W    = (const float*)d_in[3];  // [100, 200]
    const float* b    = (const float*)d_in[4];  // [100]
    const float* Wp   = (const float*)d_in[5];  // [2, 100]
    const float* bp   = (const float*)d_in[6];  // [2]
    float* out = (float*)d_out;

    __nv_bfloat16 *Bhi, *Blo;
    float *WTt, *h0, *t1, *t2;
    cudaGetSymbolAddress((void**)&Bhi, g_Bhi);
    cudaGetSymbolAddress((void**)&Blo, g_Blo);
    cudaGetSymbolAddress((void**)&WTt, g_WTt);
    cudaGetSymbolAddress((void**)&h0, g_h0);
    cudaGetSymbolAddress((void**)&t1, g_t1);
    cudaGetSymbolAddress((void**)&t2, g_t2);

    static int attr_set = 0;
    if (!attr_set) {
        cudaFuncSetAttribute(leaf_gemm_mma, cudaFuncAttributeMaxDynamicSharedMemorySize,
                             LEAF_SMEM);
        cudaFuncSetAttribute(tree_stage1, cudaFuncAttributeMaxDynamicSharedMemorySize,
                             TREE_SMEM);
        cudaFuncSetAttribute(tree_stage2, cudaFuncAttributeMaxDynamicSharedMemorySize,
                             TREE_SMEM);
        cudaFuncSetAttribute(tree_stage3, cudaFuncAttributeMaxDynamicSharedMemorySize,
                             TREE_SMEM);
        attr_set = 1;
    }

    prep_B<<<(128 * 4096 + 255) / 256, 256>>>(We, Bhi, Blo);
    prep_WTt<<<(200 * 100 + 255) / 256, 256>>>(W, WTt);

    leaf_gemm_mma<<<128, 256, LEAF_SMEM>>>(leaf, Bhi, Blo, be, h0);

    tree_stage1<<<256, 256, TREE_SMEM>>>(h0, t1, WTt, b);
    tree_stage2<<<16, 256, TREE_SMEM>>>(t1, t2, WTt, b);
    tree_stage3<<<1, 256, TREE_SMEM>>>(t2, out, WTt, b, Wp, bp);
}

// round 8
// speedup vs baseline: 5.1658x; 1.0805x over previous
#include <cuda_runtime.h>
#include <cuda_bf16.h>
#include <cstdint>

// ===========================================================================
// Tree-RNN round 7:
//  - leaf GEMM: mma.sync.m16n8k16 bf16, 3-term split; 512 threads (16 warps),
//    BK=64, 2-stage cp.async pipeline, 144B-padded smem rows.
//  - tree: 128 blocks x 64 leaves x 6 levels -> 8 blocks x 16 x 4 -> 1 block
//    x 8 x 3 + projection.
// ===========================================================================

// ----------------------------- scratch ------------------------------------
__device__ __nv_bfloat16 g_Bhi[128 * 4096];  // We padded to 128 rows, bf16 hi
__device__ __nv_bfloat16 g_Blo[128 * 4096];  // residual lo
__device__ float g_WTt[200 * 100];           // W k-major
__device__ float g_h0[8192 * 100];
__device__ float g_t1[128 * 100];
__device__ float g_t2[8 * 100];

// ----------------------------- helpers ------------------------------------
__device__ __forceinline__ void cp16(uint32_t saddr, const void* g) {
    asm volatile("cp.async.cg.shared.global [%0], [%1], 16;" :: "r"(saddr), "l"(g));
}
__device__ __forceinline__ void cp_commit() { asm volatile("cp.async.commit_group;"); }
__device__ __forceinline__ void cp_wait0()  { asm volatile("cp.async.wait_group 0;"); }

__device__ __forceinline__ void ldsm_x4(uint32_t& r0, uint32_t& r1, uint32_t& r2,
                                        uint32_t& r3, uint32_t addr) {
    asm volatile("ldmatrix.sync.aligned.m8n8.x4.shared.b16 {%0,%1,%2,%3}, [%4];"
                 : "=r"(r0), "=r"(r1), "=r"(r2), "=r"(r3) : "r"(addr));
}
__device__ __forceinline__ void mma16816(float* c, const uint32_t* a, const uint32_t* b) {
    asm volatile(
        "mma.sync.aligned.m16n8k16.row.col.f32.bf16.bf16.f32 "
        "{%0,%1,%2,%3}, {%4,%5,%6,%7}, {%8,%9}, {%0,%1,%2,%3};"
        : "+f"(c[0]), "+f"(c[1]), "+f"(c[2]), "+f"(c[3])
        : "r"(a[0]), "r"(a[1]), "r"(a[2]), "r"(a[3]), "r"(b[0]), "r"(b[1]));
}

// split 8 fp32 -> hi/lo bf16x2 uint4 pair
__device__ __forceinline__ void split8(float4 a, float4 b, uint4& hv, uint4& lv) {
    __nv_bfloat162 h0 = __float22bfloat162_rn(make_float2(a.x, a.y));
    __nv_bfloat162 h1 = __float22bfloat162_rn(make_float2(a.z, a.w));
    __nv_bfloat162 h2 = __float22bfloat162_rn(make_float2(b.x, b.y));
    __nv_bfloat162 h3 = __float22bfloat162_rn(make_float2(b.z, b.w));
    float2 f0 = __bfloat1622float2(h0), f1 = __bfloat1622float2(h1);
    float2 f2 = __bfloat1622float2(h2), f3 = __bfloat1622float2(h3);
    __nv_bfloat162 l0 = __float22bfloat162_rn(make_float2(a.x - f0.x, a.y - f0.y));
    __nv_bfloat162 l1 = __float22bfloat162_rn(make_float2(a.z - f1.x, a.w - f1.y));
    __nv_bfloat162 l2 = __float22bfloat162_rn(make_float2(b.x - f2.x, b.y - f2.y));
    __nv_bfloat162 l3 = __float22bfloat162_rn(make_float2(b.z - f3.x, b.w - f3.y));
    hv = make_uint4(*(uint32_t*)&h0, *(uint32_t*)&h1, *(uint32_t*)&h2, *(uint32_t*)&h3);
    lv = make_uint4(*(uint32_t*)&l0, *(uint32_t*)&l1, *(uint32_t*)&l2, *(uint32_t*)&l3);
}

// ----------------------------- prep kernels --------------------------------
__global__ void prep_B(const float* __restrict__ We,
                       __nv_bfloat16* __restrict__ bhi, __nv_bfloat16* __restrict__ blo) {
    int idx = blockIdx.x * blockDim.x + threadIdx.x;
    if (idx >= 128 * 4096) return;
    int n = idx >> 12;
    float v = (n < 100) ? We[idx] : 0.0f;
    __nv_bfloat16 h = __float2bfloat16(v);
    bhi[idx] = h;
    blo[idx] = __float2bfloat16(v - __bfloat162float(h));
}
__global__ void prep_WTt(const float* __restrict__ W, float* __restrict__ dst) {
    int idx = blockIdx.x * blockDim.x + threadIdx.x;
    if (idx >= 200 * 100) return;
    int k = idx / 100, n = idx % 100;
    dst[idx] = W[n * 200 + k];
}

// ----------------------------- leaf GEMM -----------------------------------
// C[8192,100] = relu(A[8192,4096] @ WeT + bias)
// BM=64, BN=128, BK=64; 16 warps as 4(M) x 4(N), warp tile 16x32.
// smem rows 144B (128B data + 16B pad) -> conflict-free ldsm/STS.
#define AROWB     144
#define S_AHI     0
#define S_ALO     (64 * AROWB)              // 9216
#define S_BHI     (2 * 64 * AROWB)          // 18432
#define S_BLO     (S_BHI + 128 * AROWB)     // 36864
#define LSTAGE    (S_BLO + 128 * AROWB)     // 55296
#define LEAF_SMEM (2 * LSTAGE)              // 110592

__global__ __launch_bounds__(512)
void leaf_gemm_mma(const float* __restrict__ A,
                   const __nv_bfloat16* __restrict__ Bhi,
                   const __nv_bfloat16* __restrict__ Blo,
                   const float* __restrict__ bias,
                   float* __restrict__ C) {
    extern __shared__ char smem[];
    const uint32_t sbase = (uint32_t)__cvta_generic_to_shared(smem);

    const int tid  = threadIdx.x;
    const int lane = tid & 31;
    const int wid  = tid >> 5;
    const int wm   = wid >> 2;       // 0..3 (16 rows each)
    const int wn   = wid & 3;        // 0..3 (32 cols each)
    const int row0 = blockIdx.x * 64;

    const int mat = lane >> 3, r8 = lane & 7;
    const uint32_t aoff =
        (uint32_t)((wm * 16 + (mat & 1) * 8 + r8) * AROWB + (mat >> 1) * 16);
    uint32_t boff[2];
#pragma unroll
    for (int nt = 0; nt < 2; nt++)
        boff[nt] = (uint32_t)((wn * 32 + nt * 16 + (mat >> 1) * 8 + r8) * AROWB +
                              (mat & 1) * 16);

    // A loads: 64 rows x 64 k fp32 -> 8 floats/thread
    const int ar  = tid >> 3;
    const int aks = tid & 7;
    const float* agp = A + (size_t)(row0 + ar) * 4096 + aks * 8;
    const uint32_t adof = (uint32_t)(ar * AROWB + aks * 16);

    const char* bhp = (const char*)Bhi;
    const char* blp = (const char*)Blo;

    float acc[4][4];
#pragma unroll
    for (int j = 0; j < 4; j++)
#pragma unroll
        for (int c = 0; c < 4; c++) acc[j][c] = 0.0f;

    float4 av0, av1;

    // ---- prologue: chunk 0 ----
    {
#pragma unroll
        for (int q = 0; q < 2; q++) {
            int idx = tid + q * 512;
            int brow = idx >> 3, seg = idx & 7;
            uint32_t dof = (uint32_t)(brow * AROWB + seg * 16);
            size_t gof = (size_t)brow * 8192 + seg * 16;
            cp16(sbase + S_BHI + dof, bhp + gof);
            cp16(sbase + S_BLO + dof, blp + gof);
        }
        cp_commit();
        av0 = *(const float4*)(agp);
        av1 = *(const float4*)(agp + 4);
        uint4 hv, lv;
        split8(av0, av1, hv, lv);
        *(uint4*)(smem + S_AHI + adof) = hv;
        *(uint4*)(smem + S_ALO + adof) = lv;
    }

    for (int i = 0; i < 64; i++) {
        const int s = i & 1;
        const uint32_t st = sbase + s * LSTAGE;
        const uint32_t nst = sbase + (s ^ 1) * LSTAGE;
        char* nst_gen = smem + (s ^ 1) * LSTAGE;

        cp_wait0();          // B chunk i resident
        __syncthreads();     // A chunk i visible; stage s^1 free

        if (i < 63) {
            const size_t kb = (size_t)(i + 1) * 128;  // bytes along K (64 bf16)
#pragma unroll
            for (int q = 0; q < 2; q++) {
                int idx = tid + q * 512;
                int brow = idx >> 3, seg = idx & 7;
                uint32_t dof = (uint32_t)(brow * AROWB + seg * 16);
                size_t gof = (size_t)brow * 8192 + kb + seg * 16;
                cp16(nst + S_BHI + dof, bhp + gof);
                cp16(nst + S_BLO + dof, blp + gof);
            }
            cp_commit();
            const float* ap = agp + (size_t)(i + 1) * 64;
            av0 = *(const float4*)(ap);
            av1 = *(const float4*)(ap + 4);
        }

        // ---- compute chunk i: 4 x k16 ----
#pragma unroll
        for (int kk = 0; kk < 4; kk++) {
            const uint32_t kb = (uint32_t)(kk * 32);
            uint32_t ah[4], al[4], bh[2][4], bl[2][4];
            ldsm_x4(ah[0], ah[1], ah[2], ah[3], st + S_AHI + aoff + kb);
            ldsm_x4(al[0], al[1], al[2], al[3], st + S_ALO + aoff + kb);
#pragma unroll
            for (int nt = 0; nt < 2; nt++) {
                ldsm_x4(bh[nt][0], bh[nt][1], bh[nt][2], bh[nt][3],
                        st + S_BHI + boff[nt] + kb);
                ldsm_x4(bl[nt][0], bl[nt][1], bl[nt][2], bl[nt][3],
                        st + S_BLO + boff[nt] + kb);
            }
#pragma unroll
            for (int j = 0; j < 4; j++) {
                const int nt = j >> 1, p = (j & 1) * 2;
                uint32_t bhr[2] = {bh[nt][p], bh[nt][p + 1]};
                uint32_t blr[2] = {bl[nt][p], bl[nt][p + 1]};
                mma16816(acc[j], ah, bhr);   // hi*hi
                mma16816(acc[j], ah, blr);   // hi*lo
                mma16816(acc[j], al, bhr);   // lo*hi
            }
        }

        // ---- convert + STS A chunk i+1 into stage s^1 ----
        if (i < 63) {
            uint4 hv, lv;
            split8(av0, av1, hv, lv);
            *(uint4*)(nst_gen + S_AHI + adof) = hv;
            *(uint4*)(nst_gen + S_ALO + adof) = lv;
        }
    }

    // ---- epilogue ----
    const int row = row0 + wm * 16 + (lane >> 2);
#pragma unroll
    for (int j = 0; j < 4; j++) {
        const int col = wn * 32 + j * 8 + (lane & 3) * 2;
#pragma unroll
        for (int c = 0; c < 4; c++) {
            const int rr = row + (c >> 1) * 8;
            const int cc = col + (c & 1);
            if (cc < 100)
                C[(size_t)rr * 100 + cc] =
                    fmaxf(acc[j][c] + __ldg(bias + cc), 0.0f);
        }
    }
}

// ----------------------------- tree cascade --------------------------------
__device__ __forceinline__ void run_level(const float* __restrict__ Ws,
                                          const float* __restrict__ sb,
                                          const float* __restrict__ xin,
                                          float* __restrict__ xout, int m_out) {
    const int n = threadIdx.x & 127;
    const int half = threadIdx.x >> 7;
    for (int t = 0; t < m_out; t += 16) {
        if (n < 100) {
            float acc[8];
#pragma unroll
            for (int c = 0; c < 8; c++) acc[c] = 0.0f;
            for (int k0 = 0; k0 < 200; k0 += 8) {
                float w[8];
#pragma unroll
                for (int j = 0; j < 8; j++) w[j] = Ws[(k0 + j) * 100 + n];
#pragma unroll
                for (int c = 0; c < 8; c++) {
                    int nd = t + half + 2 * c;
                    if (nd < m_out) {
                        float4 x0 = *(const float4*)(xin + nd * 200 + k0);
                        float4 x1 = *(const float4*)(xin + nd * 200 + k0 + 4);
                        acc[c] = fmaf(x0.x, w[0], acc[c]);
                        acc[c] = fmaf(x0.y, w[1], acc[c]);
                        acc[c] = fmaf(x0.z, w[2], acc[c]);
                        acc[c] = fmaf(x0.w, w[3], acc[c]);
                        acc[c] = fmaf(x1.x, w[4], acc[c]);
                        acc[c] = fmaf(x1.y, w[5], acc[c]);
                        acc[c] = fmaf(x1.z, w[6], acc[c]);
                        acc[c] = fmaf(x1.w, w[7], acc[c]);
                    }
                }
            }
#pragma unroll
            for (int c = 0; c < 8; c++) {
                int nd = t + half + 2 * c;
                if (nd < m_out) xout[nd * 100 + n] = fmaxf(acc[c] + sb[n], 0.0f);
            }
        }
    }
    __syncthreads();
}

template <int ROWS_IN, int NLEV>
__device__ __forceinline__ const float* tree_body(const float* __restrict__ in_rows,
                                                  const float* __restrict__ Wt,
                                                  const float* __restrict__ b,
                                                  float* sm) {
    float* Ws   = sm;
    float* sb   = sm + 20000;
    float* bufA = sm + 20100;
    float* bufB = bufA + ROWS_IN * 100;

    for (int i = threadIdx.x; i < 20000; i += 256) Ws[i] = Wt[i];
    if (threadIdx.x < 100) sb[threadIdx.x] = b[threadIdx.x];
    for (int i = threadIdx.x; i < ROWS_IN * 100; i += 256) bufA[i] = in_rows[i];
    __syncthreads();

    const float* cur = bufA;
    float* nxt = bufB;
    int m = ROWS_IN;
#pragma unroll
    for (int l = 0; l < NLEV; l++) {
        run_level(Ws, sb, cur, nxt, m >> 1);
        const float* t = cur; cur = nxt; nxt = (float*)t;
        m >>= 1;
    }
    return cur;
}

#define TREE_SMEM_1 ((20100 + 6400 + 3200) * 4)   // 118800
#define TREE_SMEM_2 ((20100 + 1600 + 800) * 4)    // 90000
#define TREE_SMEM_3 ((20100 + 800 + 400) * 4)     // 85200

__global__ __launch_bounds__(256)
void tree_stage1(const float* __restrict__ in, float* __restrict__ out,
                 const float* __restrict__ Wt, const float* __restrict__ b) {
    extern __shared__ float sm[];
    const float* res = tree_body<64, 6>(in + (size_t)blockIdx.x * 6400, Wt, b, sm);
    if (threadIdx.x < 100) out[blockIdx.x * 100 + threadIdx.x] = res[threadIdx.x];
}
__global__ __launch_bounds__(256)
void tree_stage2(const float* __restrict__ in, float* __restrict__ out,
                 const float* __restrict__ Wt, const float* __restrict__ b) {
    extern __shared__ float sm[];
    const float* res = tree_body<16, 4>(in + (size_t)blockIdx.x * 1600, Wt, b, sm);
    if (threadIdx.x < 100) out[blockIdx.x * 100 + threadIdx.x] = res[threadIdx.x];
}
__global__ __launch_bounds__(256)
void tree_stage3(const float* __restrict__ in, float* __restrict__ out,
                 const float* __restrict__ Wt, const float* __restrict__ b,
                 const float* __restrict__ Wp, const float* __restrict__ bp) {
    extern __shared__ float sm[];
    const float* res = tree_body<8, 3>(in, Wt, b, sm);
    if (threadIdx.x < 64) {
        const int c = threadIdx.x >> 5;
        const int lane = threadIdx.x & 31;
        float s = 0.0f;
        for (int k = lane; k < 100; k += 32) s += Wp[c * 100 + k] * res[k];
#pragma unroll
        for (int o = 16; o > 0; o >>= 1) s += __shfl_down_sync(0xffffffffu, s, o);
        if (lane == 0) out[c] = s + bp[c];
    }
}

// ------------------------------ launch -------------------------------------
extern "C" void kernel_launch(void* const* d_in, const int* in_sizes, int n_in,
                              void* d_out, int out_size) {
    const float* leaf = (const float*)d_in[0];  // [8192, 4096]
    const float* We   = (const float*)d_in[1];  // [100, 4096]
    const float* be   = (const float*)d_in[2];  // [100]
    const float* W    = (const float*)d_in[3];  // [100, 200]
    const float* b    = (const float*)d_in[4];  // [100]
    const float* Wp   = (const float*)d_in[5];  // [2, 100]
    const float* bp   = (const float*)d_in[6];  // [2]
    float* out = (float*)d_out;

    __nv_bfloat16 *Bhi, *Blo;
    float *WTt, *h0, *t1, *t2;
    cudaGetSymbolAddress((void**)&Bhi, g_Bhi);
    cudaGetSymbolAddress((void**)&Blo, g_Blo);
    cudaGetSymbolAddress((void**)&WTt, g_WTt);
    cudaGetSymbolAddress((void**)&h0, g_h0);
    cudaGetSymbolAddress((void**)&t1, g_t1);
    cudaGetSymbolAddress((void**)&t2, g_t2);

    static int attr_set = 0;
    if (!attr_set) {
        cudaFuncSetAttribute(leaf_gemm_mma, cudaFuncAttributeMaxDynamicSharedMemorySize,
                             LEAF_SMEM);
        cudaFuncSetAttribute(tree_stage1, cudaFuncAttributeMaxDynamicSharedMemorySize,
                             TREE_SMEM_1);
        cudaFuncSetAttribute(tree_stage2, cudaFuncAttributeMaxDynamicSharedMemorySize,
                             TREE_SMEM_2);
        cudaFuncSetAttribute(tree_stage3, cudaFuncAttributeMaxDynamicSharedMemorySize,
                             TREE_SMEM_3);
        attr_set = 1;
    }

    prep_B<<<(128 * 4096 + 255) / 256, 256>>>(We, Bhi, Blo);
    prep_WTt<<<(200 * 100 + 255) / 256, 256>>>(W, WTt);

    leaf_gemm_mma<<<128, 512, LEAF_SMEM>>>(leaf, Bhi, Blo, be, h0);

    tree_stage1<<<128, 256, TREE_SMEM_1>>>(h0, t1, WTt, b);
    tree_stage2<<<8, 256, TREE_SMEM_2>>>(t1, t2, WTt, b);
    tree_stage3<<<1, 256, TREE_SMEM_3>>>(t2, out, WTt, b, Wp, bp);
}